// round 10
// baseline (speedup 1.0000x reference)
#include <cuda_runtime.h>
#include <cuda_bf16.h>
#include <math.h>

typedef unsigned int u32; typedef unsigned long long u64;
typedef __nv_bfloat16 bf16;

#define MAXN 100096
#define MAXM (3*MAXN)
__device__ float g_v  [(size_t)MAXN*1536];
__device__ float g_dot[(size_t)MAXN*256];
__device__ bf16 g_vh [(size_t)MAXM*256];
__device__ bf16 g_vl [(size_t)MAXM*256];
__device__ bf16 g_hch[(size_t)MAXN*512];
__device__ bf16 g_hcl[(size_t)MAXN*512];
__device__ bf16 g_hh [(size_t)MAXN*256];
__device__ bf16 g_hl [(size_t)MAXN*256];
__device__ bf16 g_Weh[512*256],  g_Wel[512*256];   // [n][k]
__device__ bf16 g_W1h[256*512],  g_W1l[256*512];   // [n][k]
__device__ bf16 g_W2h[1024*256], g_W2l[1024*256];  // [nc][k], quad-interleaved+pad

#define RS 20
#define ASTRIDE 2560
#define SMEM_BYTES (8*ASTRIDE*4)
#define TS 132

__device__ __forceinline__ void splt(float f0, float f1, u32 &hi, u32 &lo){
  __nv_bfloat162 h = __floats2bfloat162_rn(f0, f1);
  __nv_bfloat162 l = __floats2bfloat162_rn(f0 - __bfloat162float(h.x),
                                           f1 - __bfloat162float(h.y));
  hi = *(u32*)&h; lo = *(u32*)&l;
}
__device__ __forceinline__ void mma16816(float* d, const u32* a, u32 b0, u32 b1){
  asm volatile("mma.sync.aligned.m16n8k16.row.col.f32.bf16.bf16.f32 "
    "{%0,%1,%2,%3},{%4,%5,%6,%7},{%8,%9},{%0,%1,%2,%3};"
    : "+f"(d[0]),"+f"(d[1]),"+f"(d[2]),"+f"(d[3])
    : "r"(a[0]),"r"(a[1]),"r"(a[2]),"r"(a[3]),"r"(b0),"r"(b1));
}
__device__ __forceinline__ void ldm4(u32* r, u32 addr){
  asm volatile("ldmatrix.sync.aligned.m8n8.x4.shared.b16 {%0,%1,%2,%3},[%4];"
    : "=r"(r[0]),"=r"(r[1]),"=r"(r[2]),"=r"(r[3]) : "r"(addr));
}
__device__ __forceinline__ void ldm2(u32 &r0, u32 &r1, u32 addr){
  asm volatile("ldmatrix.sync.aligned.m8n8.x2.shared.b16 {%0,%1},[%2];"
    : "=r"(r0),"=r"(r1) : "r"(addr));
}
__device__ __forceinline__ u32 s2u(const void* p){ u32 a;
  asm("{.reg .u64 t; cvta.to.shared.u64 t,%1; cvt.u32.u64 %0,t;}":"=r"(a):"l"(p)); return a; }
__device__ __forceinline__ void cpa16(u32 dst, const void* src){
  asm volatile("cp.async.cg.shared.global [%0], [%1], 16;" :: "r"(dst), "l"(src));
}

// MODE 0: plain fp32 C.  MODE 1: +bias,silu -> bf16 hi/lo.  MODE 2: fused dx/dvec.
template<int MODE>
__global__ void __launch_bounds__(128, 2)
gemm_k(const bf16* __restrict__ Ah, const bf16* __restrict__ Al,
       const bf16* __restrict__ Bh, const bf16* __restrict__ Bl,
       const float* __restrict__ bias,
       void* o0, void* o1, const float* __restrict__ gdot,
       const float* __restrict__ gv,
       int M, int K, int N, int nnodes)
{
  extern __shared__ u32 sm[];
  const u32 sbase = s2u(sm);
  const int tid = threadIdx.x, lane = tid & 31, wid = tid >> 5;
  const int wm = (wid & 1) * 64, wn = (wid >> 1) * 64;
  const int m0 = blockIdx.y * 128, n0 = blockIdx.x * 128;
  const int g = lane >> 2, qq = lane & 3;
  const int NK = K >> 5;

  float acc[4][8][4];
  #pragma unroll
  for (int a=0;a<4;a++) for (int b=0;b<8;b++) for (int c=0;c<4;c++) acc[a][b][c]=0.f;

  const int srow = tid >> 2, sc = tid & 3;
  auto stage = [&](int s, int kc){
    #pragma unroll
    for (int q = 0; q < 16; q++){
      const int a   = q >> 2;
      const int row = (q & 3) * 32 + srow;
      const u32 dst = sbase + ((s*4 + a)*ASTRIDE + row*RS + sc*4) * 4;
      const bf16* src;
      if (a < 2){
        int gr = m0 + row; if (gr >= M) gr = M - 1;
        src = (a == 0 ? Ah : Al) + (size_t)gr * K + kc + sc*8;
      } else {
        src = (a == 2 ? Bh : Bl) + (size_t)(n0 + row) * K + kc + sc*8;
      }
      cpa16(dst, src);
    }
    asm volatile("cp.async.commit_group;" ::: "memory");
  };

  // ldmatrix lane-address offsets (words)
  const int aoff = (wm + (lane & 7) + ((lane >> 3) & 1) * 8) * RS + ((lane >> 4) & 1) * 4;
  const int boff = (wn + (lane & 7)) * RS + ((lane >> 3) & 1) * 4;

  stage(0, 0);
  for (int it = 0; it < NK; it++){
    if (it + 1 < NK){
      stage((it + 1) & 1, (it + 1) << 5);
      asm volatile("cp.async.wait_group 1;" ::: "memory");
    } else {
      asm volatile("cp.async.wait_group 0;" ::: "memory");
    }
    __syncthreads();
    const u32 base = sbase + ((it & 1) * 4) * ASTRIDE * 4;
    const u32 bAh = base, bAl = base + ASTRIDE*4;
    const u32 bBh = base + 2*ASTRIDE*4, bBl = base + 3*ASTRIDE*4;

    #pragma unroll
    for (int k16 = 0; k16 < 2; k16++){
      const int kof = (aoff + k16*8) * 4;
      const int kofb = (boff + k16*8) * 4;
      u32 ah[4][4], al[4][4];
      #pragma unroll
      for (int fm = 0; fm < 4; fm++){
        ldm4(ah[fm], bAh + kof + fm*16*RS*4);
        ldm4(al[fm], bAl + kof + fm*16*RS*4);
      }
      #pragma unroll
      for (int fn = 0; fn < 8; fn++){
        u32 bh0, bh1, bl0, bl1;
        ldm2(bh0, bh1, bBh + kofb + fn*8*RS*4);
        ldm2(bl0, bl1, bBl + kofb + fn*8*RS*4);
        #pragma unroll
        for (int fm = 0; fm < 4; fm++){
          mma16816(acc[fm][fn], ah[fm], bh0, bh1);
          mma16816(acc[fm][fn], al[fm], bh0, bh1);
          mma16816(acc[fm][fn], ah[fm], bl0, bl1);
        }
      }
    }
    __syncthreads();
  }

  if (MODE == 0){
    float* C = (float*)o0;
    #pragma unroll
    for (int fm = 0; fm < 4; fm++)
      #pragma unroll
      for (int half = 0; half < 2; half++){
        const int row = m0 + wm + fm*16 + g + half*8;
        if (row >= M) continue;
        #pragma unroll
        for (int fn = 0; fn < 8; fn++){
          const int col = n0 + wn + fn*8 + 2*qq;
          *(float2*)&C[(size_t)row*N + col] =
              make_float2(acc[fm][fn][half*2], acc[fm][fn][half*2+1]);
        }
      }
    return;
  }
  if (MODE == 1){
    bf16* Ch = (bf16*)o0; bf16* Cl = (bf16*)o1;
    #pragma unroll
    for (int fm = 0; fm < 4; fm++)
      #pragma unroll
      for (int half = 0; half < 2; half++){
        const int row = m0 + wm + fm*16 + g + half*8;
        if (row >= M) continue;
        #pragma unroll
        for (int fn = 0; fn < 8; fn++){
          const int col = n0 + wn + fn*8 + 2*qq;
          float2 bb = *(const float2*)(bias + col);
          float v0 = acc[fm][fn][half*2]   + bb.x;
          float v1 = acc[fm][fn][half*2+1] + bb.y;
          v0 = v0 / (1.f + __expf(-v0));
          v1 = v1 / (1.f + __expf(-v1));
          u32 h, l; splt(v0, v1, h, l);
          ((u32*)Ch)[((size_t)row*N + col) >> 1] = h;
          ((u32*)Cl)[((size_t)row*N + col) >> 1] = l;
        }
      }
    return;
  }

  // MODE 2: dump acc to smem, fused dx/dvec epilogue (cols quad-interleaved)
  float* smf = (float*)sm;
  #pragma unroll
  for (int fm = 0; fm < 4; fm++)
    #pragma unroll
    for (int half = 0; half < 2; half++){
      const int row = wm + fm*16 + g + half*8;
      #pragma unroll
      for (int fn = 0; fn < 8; fn++){
        const int col = wn + fn*8 + 2*qq;
        *(float2*)&smf[row*TS + col] =
            make_float2(acc[fm][fn][half*2], acc[fm][fn][half*2+1]);
      }
    }
  __syncthreads();
  {
    float* out = (float*)o0;
    const float is2 = 0.70710678118654752f;
    for (int id = tid; id < 128*32; id += 128){
      const int nd = id >> 5, j = id & 31;
      const int gnd = m0 + nd;
      if (gnd >= nnodes) continue;
      const int jg = (n0 >> 2) + j;
      const float* rr = smf + nd*TS + 4*j;
      float x1 = rr[0] + bias[jg];
      float x2 = rr[1] + bias[256 + jg];
      float x3 = rr[2] + bias[512 + jg];
      out[(size_t)gnd*256 + jg] =
          (x1 + x2 + gdot[(size_t)gnd*256 + jg]) * is2;
      float* dv = out + (size_t)nnodes*256 + (size_t)gnd*768;
      const float* v2 = gv + (size_t)gnd*1536 + 256;
      dv[      jg] = x3 * v2[       jg];
      dv[256 + jg] = x3 * v2[512  + jg];
      dv[512 + jg] = x3 * v2[1024 + jg];
    }
  }
}

__global__ void wconv(const float* __restrict__ W, bf16* Wh, bf16* Wl, int K, int N){
  int idx = blockIdx.x*256 + threadIdx.x;
  if (idx >= K*N) return;
  int k = idx / N, nn = idx - k*N;
  float f = W[idx];
  bf16 h = __float2bfloat16_rn(f);
  Wh[(size_t)nn*K + k] = h;
  Wl[(size_t)nn*K + k] = __float2bfloat16_rn(f - __bfloat162float(h));
}
__global__ void wconv_2(const float* __restrict__ W, bf16* Wh, bf16* Wl){
  int idx = blockIdx.x*256 + threadIdx.x;          // 256*1024
  if (idx >= 256*1024) return;
  int k = idx >> 10, nc = idx & 1023;
  int j = nc >> 2, c = nc & 3;
  float f = (c < 3) ? W[k*768 + c*256 + j] : 0.f;
  bf16 h = __float2bfloat16_rn(f);
  Wh[(size_t)nc*256 + k] = h;
  Wl[(size_t)nc*256 + k] = __float2bfloat16_rn(f - __bfloat162float(h));
}
__global__ void aconv(const float* __restrict__ A, bf16* Ahh, bf16* All, int n4){
  int i = blockIdx.x*256 + threadIdx.x;
  if (i >= n4) return;
  float4 v = ((const float4*)A)[i];
  u32 h0,l0,h1,l1;
  splt(v.x, v.y, h0, l0); splt(v.z, v.w, h1, l1);
  ((uint2*)Ahh)[i] = make_uint2(h0, h1);
  ((uint2*)All)[i] = make_uint2(l0, l1);
}
__global__ void glue1(const float* __restrict__ x, int n){
  int nd = blockIdx.x, j = threadIdx.x;
  const float* vr = g_v + (size_t)nd*1536;
  float a0=vr[j], a1=vr[512+j], a2=vr[1024+j];
  float b0=vr[256+j], b1=vr[768+j], b2=vr[1280+j];
  float xx = x[(size_t)nd*256 + j];
  float sc = sqrtf(a0*a0 + a1*a1 + a2*a2);
  g_dot[(size_t)nd*256 + j] = (a0*b0 + a1*b1 + a2*b2) * 0.0625f;
  size_t o0 = (size_t)nd*512 + j, o1 = o0 + 256;
  bf16 xh = __float2bfloat16_rn(xx);
  bf16 sh = __float2bfloat16_rn(sc);
  g_hch[o0] = xh; g_hcl[o0] = __float2bfloat16_rn(xx - __bfloat162float(xh));
  g_hch[o1] = sh; g_hcl[o1] = __float2bfloat16_rn(sc - __bfloat162float(sh));
}

extern "C" void kernel_launch(void* const* d_in, const int* in_sizes, int n_in,
                              void* d_out, int out_size)
{
  const float* x   = (const float*)d_in[0];
  const float* vec = (const float*)d_in[1];
  const float* We  = (const float*)d_in[3];
  const float* W1  = (const float*)d_in[4];
  const float* b1  = (const float*)d_in[5];
  const float* W2  = (const float*)d_in[6];
  const float* b2  = (const float*)d_in[7];
  float* out = (float*)d_out;
  const int n = in_sizes[0] / 256;
  const int M1 = 3*n;

  float *pv, *pdot;
  bf16 *pvh,*pvl,*phch,*phcl,*phh,*phl,*pWeh,*pWel,*pW1h,*pW1l,*pW2h,*pW2l;
  cudaGetSymbolAddress((void**)&pv,  g_v);   cudaGetSymbolAddress((void**)&pdot,g_dot);
  cudaGetSymbolAddress((void**)&pvh, g_vh);  cudaGetSymbolAddress((void**)&pvl, g_vl);
  cudaGetSymbolAddress((void**)&phch,g_hch); cudaGetSymbolAddress((void**)&phcl,g_hcl);
  cudaGetSymbolAddress((void**)&phh, g_hh);  cudaGetSymbolAddress((void**)&phl, g_hl);
  cudaGetSymbolAddress((void**)&pWeh,g_Weh); cudaGetSymbolAddress((void**)&pWel,g_Wel);
  cudaGetSymbolAddress((void**)&pW1h,g_W1h); cudaGetSymbolAddress((void**)&pW1l,g_W1l);
  cudaGetSymbolAddress((void**)&pW2h,g_W2h); cudaGetSymbolAddress((void**)&pW2l,g_W2l);

  cudaFuncSetAttribute(gemm_k<0>, cudaFuncAttributeMaxDynamicSharedMemorySize, SMEM_BYTES);
  cudaFuncSetAttribute(gemm_k<1>, cudaFuncAttributeMaxDynamicSharedMemorySize, SMEM_BYTES);
  cudaFuncSetAttribute(gemm_k<2>, cudaFuncAttributeMaxDynamicSharedMemorySize, SMEM_BYTES);

  wconv<<<(256*512+255)/256, 256>>>(We, pWeh, pWel, 256, 512);
  wconv<<<(512*256+255)/256, 256>>>(W1, pW1h, pW1l, 512, 256);
  wconv_2<<<(256*1024+255)/256, 256>>>(W2, pW2h, pW2l);
  aconv<<<((M1*64)+255)/256, 256>>>(vec, pvh, pvl, M1*64);

  gemm_k<0><<<dim3(4,(M1+127)/128), 128, SMEM_BYTES>>>(
      pvh, pvl, pWeh, pWel, (const float*)0,
      pv, (void*)0, (const float*)0, (const float*)0, M1, 256, 512, n);
  glue1<<<n, 256>>>(x, n);
  gemm_k<1><<<dim3(2,(n+127)/128), 128, SMEM_BYTES>>>(
      phch, phcl, pW1h, pW1l, b1,
      phh, phl, (const float*)0, (const float*)0, n, 512, 256, n);
  gemm_k<2><<<dim3(8,(n+127)/128), 128, SMEM_BYTES>>>(
      phh, phl, pW2h, pW2l, b2,
      out, (void*)0, pdot, pv, n, 256, 1024, n);
}

// round 11
// speedup vs baseline: 1.1292x; 1.1292x over previous
#include <cuda_runtime.h>
#include <cuda_bf16.h>
#include <math.h>

typedef unsigned int u32; typedef unsigned long long u64;
typedef __nv_bfloat16 bf16;

#define MAXN 100096
#define MAXM (3*MAXN)
__device__ float g_v  [(size_t)MAXN*1536];
__device__ float g_xv [(size_t)MAXN*768];
__device__ float g_dot[(size_t)MAXN*256];
__device__ bf16 g_vh [(size_t)MAXM*256];
__device__ bf16 g_vl [(size_t)MAXM*256];
__device__ bf16 g_hch[(size_t)MAXN*512];
__device__ bf16 g_hcl[(size_t)MAXN*512];
__device__ bf16 g_hh [(size_t)MAXN*256];
__device__ bf16 g_hl [(size_t)MAXN*256];
__device__ bf16 g_Weh[512*256], g_Wel[512*256];
__device__ bf16 g_W1h[256*512], g_W1l[256*512];
__device__ bf16 g_W2h[768*256], g_W2l[768*256];

#define RS 20
#define ASTRIDE 2560
#define SMEM_BYTES (8*ASTRIDE*4)   // 80KB

__device__ __forceinline__ void splt(float f0, float f1, u32 &hi, u32 &lo){
  __nv_bfloat162 h = __floats2bfloat162_rn(f0, f1);
  __nv_bfloat162 l = __floats2bfloat162_rn(f0 - __bfloat162float(h.x),
                                           f1 - __bfloat162float(h.y));
  hi = *(u32*)&h; lo = *(u32*)&l;
}
__device__ __forceinline__ void mma16816(float* d, const u32* a, u32 b0, u32 b1){
  asm volatile("mma.sync.aligned.m16n8k16.row.col.f32.bf16.bf16.f32 "
    "{%0,%1,%2,%3},{%4,%5,%6,%7},{%8,%9},{%0,%1,%2,%3};"
    : "+f"(d[0]),"+f"(d[1]),"+f"(d[2]),"+f"(d[3])
    : "r"(a[0]),"r"(a[1]),"r"(a[2]),"r"(a[3]),"r"(b0),"r"(b1));
}
__device__ __forceinline__ void ldm4(u32* r, u32 addr){
  asm volatile("ldmatrix.sync.aligned.m8n8.x4.shared.b16 {%0,%1,%2,%3},[%4];"
    : "=r"(r[0]),"=r"(r[1]),"=r"(r[2]),"=r"(r[3]) : "r"(addr));
}
__device__ __forceinline__ void ldm2(u32 &r0, u32 &r1, u32 addr){
  asm volatile("ldmatrix.sync.aligned.m8n8.x2.shared.b16 {%0,%1},[%2];"
    : "=r"(r0),"=r"(r1) : "r"(addr));
}
__device__ __forceinline__ u32 s2u(const void* p){ u32 a;
  asm("{.reg .u64 t; cvta.to.shared.u64 t,%1; cvt.u32.u64 %0,t;}":"=r"(a):"l"(p)); return a; }
__device__ __forceinline__ void cpa16(u32 dst, const void* src){
  asm volatile("cp.async.cg.shared.global [%0], [%1], 16;" :: "r"(dst), "l"(src));
}

// MODE 0: plain fp32 out. MODE 1: +bias, silu -> bf16 hi/lo. MODE 2: +bias fp32 out.
template<int MODE>
__global__ void __launch_bounds__(256, 2)
gemm_k(const bf16* __restrict__ Ah, const bf16* __restrict__ Al,
       const bf16* __restrict__ Bh, const bf16* __restrict__ Bl,
       const float* __restrict__ bias,
       void* o0, void* o1, int M, int K, int N)
{
  extern __shared__ u32 sm[];
  const u32 sbase = s2u(sm);
  const int tid = threadIdx.x, lane = tid & 31, wid = tid >> 5;
  const int wm = (wid & 1) * 64, wn = (wid >> 1) * 32;
  const int m0 = blockIdx.y * 128, n0 = blockIdx.x * 128;
  const int g = lane >> 2, qq = lane & 3;
  const int NK = K >> 5;

  float acc[4][4][4];
  #pragma unroll
  for (int a=0;a<4;a++) for (int b=0;b<4;b++) for (int c=0;c<4;c++) acc[a][b][c]=0.f;

  auto stage = [&](int s, int kc){
    #pragma unroll
    for (int a = 0; a < 4; a++){
      #pragma unroll
      for (int q = 0; q < 2; q++){
        const int idx = q*256 + tid;          // 512 chunks of 16B per array
        const int row = idx >> 2, ch = idx & 3;
        const u32 dst = sbase + ((s*4 + a)*ASTRIDE + row*RS + ch*4) * 4;
        const bf16* src;
        if (a < 2){
          int gr = m0 + row; if (gr >= M) gr = M - 1;
          src = (a == 0 ? Ah : Al) + (size_t)gr * K + kc + ch*8;
        } else {
          src = (a == 2 ? Bh : Bl) + (size_t)(n0 + row) * K + kc + ch*8;
        }
        cpa16(dst, src);
      }
    }
    asm volatile("cp.async.commit_group;" ::: "memory");
  };

  // ldmatrix lane offsets (words) — verified mapping (R10 passed correctness)
  const int aoff = (wm + (lane & 7) + ((lane >> 3) & 1) * 8) * RS + ((lane >> 4) & 1) * 4;
  const int boff = (wn + (lane & 7)) * RS + ((lane >> 3) & 1) * 4;

  stage(0, 0);
  for (int it = 0; it < NK; it++){
    if (it + 1 < NK){
      stage((it + 1) & 1, (it + 1) << 5);
      asm volatile("cp.async.wait_group 1;" ::: "memory");
    } else {
      asm volatile("cp.async.wait_group 0;" ::: "memory");
    }
    __syncthreads();
    const u32 base = sbase + ((it & 1) * 4) * ASTRIDE * 4;
    const u32 bAh = base, bAl = base + ASTRIDE*4;
    const u32 bBh = base + 2*ASTRIDE*4, bBl = base + 3*ASTRIDE*4;

    #pragma unroll
    for (int k16 = 0; k16 < 2; k16++){
      const int kof  = (aoff + k16*8) * 4;
      const int kofb = (boff + k16*8) * 4;
      u32 ah[4][4], al[4][4];
      #pragma unroll
      for (int fm = 0; fm < 4; fm++){
        ldm4(ah[fm], bAh + kof + fm*16*RS*4);
        ldm4(al[fm], bAl + kof + fm*16*RS*4);
      }
      #pragma unroll
      for (int fn = 0; fn < 4; fn++){
        u32 bh0, bh1, bl0, bl1;
        ldm2(bh0, bh1, bBh + kofb + fn*8*RS*4);
        ldm2(bl0, bl1, bBl + kofb + fn*8*RS*4);
        #pragma unroll
        for (int fm = 0; fm < 4; fm++){
          mma16816(acc[fm][fn], ah[fm], bh0, bh1);
          mma16816(acc[fm][fn], al[fm], bh0, bh1);
          mma16816(acc[fm][fn], ah[fm], bl0, bl1);
        }
      }
    }
    __syncthreads();
  }

  #pragma unroll
  for (int fm = 0; fm < 4; fm++)
    #pragma unroll
    for (int half = 0; half < 2; half++){
      const int row = m0 + wm + fm*16 + g + half*8;
      if (row >= M) continue;
      #pragma unroll
      for (int fn = 0; fn < 4; fn++){
        const int col = n0 + wn + fn*8 + 2*qq;
        float v0 = acc[fm][fn][half*2], v1 = acc[fm][fn][half*2+1];
        if (MODE == 0){
          *(float2*)&((float*)o0)[(size_t)row*N + col] = make_float2(v0, v1);
        } else if (MODE == 1){
          float2 bb = *(const float2*)(bias + col);
          v0 += bb.x; v1 += bb.y;
          v0 = v0 / (1.f + __expf(-v0));
          v1 = v1 / (1.f + __expf(-v1));
          u32 h, l; splt(v0, v1, h, l);
          ((u32*)o0)[((size_t)row*N + col) >> 1] = h;
          ((u32*)o1)[((size_t)row*N + col) >> 1] = l;
        } else {
          float2 bb = *(const float2*)(bias + col);
          *(float2*)&((float*)o0)[(size_t)row*N + col] =
              make_float2(v0 + bb.x, v1 + bb.y);
        }
      }
    }
}

__global__ void wconv(const float* __restrict__ W, bf16* Wh, bf16* Wl, int K, int N){
  int idx = blockIdx.x*256 + threadIdx.x;
  if (idx >= K*N) return;
  int k = idx / N, nn = idx - k*N;
  float f = W[idx];
  bf16 h = __float2bfloat16_rn(f);
  Wh[(size_t)nn*K + k] = h;
  Wl[(size_t)nn*K + k] = __float2bfloat16_rn(f - __bfloat162float(h));
}
__global__ void aconv(const float* __restrict__ A, bf16* Ahh, bf16* All, int n4){
  int i = blockIdx.x*256 + threadIdx.x;
  if (i >= n4) return;
  float4 v = ((const float4*)A)[i];
  u32 h0,l0,h1,l1;
  splt(v.x, v.y, h0, l0); splt(v.z, v.w, h1, l1);
  ((uint2*)Ahh)[i] = make_uint2(h0, h1);
  ((uint2*)All)[i] = make_uint2(l0, l1);
}
__global__ void glue1(const float* __restrict__ x, int n){
  int nd = blockIdx.x, j = threadIdx.x;
  const float* vr = g_v + (size_t)nd*1536;
  float a0=vr[j], a1=vr[512+j], a2=vr[1024+j];
  float b0=vr[256+j], b1=vr[768+j], b2=vr[1280+j];
  float xx = x[(size_t)nd*256 + j];
  float sc = sqrtf(a0*a0 + a1*a1 + a2*a2);
  g_dot[(size_t)nd*256 + j] = (a0*b0 + a1*b1 + a2*b2) * 0.0625f;
  size_t o0 = (size_t)nd*512 + j, o1 = o0 + 256;
  bf16 xh = __float2bfloat16_rn(xx);
  bf16 sh = __float2bfloat16_rn(sc);
  g_hch[o0] = xh; g_hcl[o0] = __float2bfloat16_rn(xx - __bfloat162float(xh));
  g_hch[o1] = sh; g_hcl[o1] = __float2bfloat16_rn(sc - __bfloat162float(sh));
}
__global__ void glue2(float* __restrict__ out, int n){
  int nd = blockIdx.x, j = threadIdx.x;
  const float* xv = g_xv + (size_t)nd*768;
  float x1 = xv[j], x2 = xv[256+j], x3 = xv[512+j];
  out[(size_t)nd*256 + j] = (x1 + x2 + g_dot[(size_t)nd*256+j]) * 0.70710678118654752f;
  const float* vr = g_v + (size_t)nd*1536 + 256;
  float* dv = out + (size_t)n*256 + (size_t)nd*768;
  dv[j]     = x3 * vr[j];
  dv[256+j] = x3 * vr[512+j];
  dv[512+j] = x3 * vr[1024+j];
}

extern "C" void kernel_launch(void* const* d_in, const int* in_sizes, int n_in,
                              void* d_out, int out_size)
{
  const float* x   = (const float*)d_in[0];
  const float* vec = (const float*)d_in[1];
  const float* We  = (const float*)d_in[3];
  const float* W1  = (const float*)d_in[4];
  const float* b1  = (const float*)d_in[5];
  const float* W2  = (const float*)d_in[6];
  const float* b2  = (const float*)d_in[7];
  float* out = (float*)d_out;
  const int n = in_sizes[0] / 256;
  const int M1 = 3*n;

  float *pv, *pxv;
  bf16 *pvh,*pvl,*phch,*phcl,*phh,*phl,*pWeh,*pWel,*pW1h,*pW1l,*pW2h,*pW2l;
  cudaGetSymbolAddress((void**)&pv,  g_v);   cudaGetSymbolAddress((void**)&pxv, g_xv);
  cudaGetSymbolAddress((void**)&pvh, g_vh);  cudaGetSymbolAddress((void**)&pvl, g_vl);
  cudaGetSymbolAddress((void**)&phch,g_hch); cudaGetSymbolAddress((void**)&phcl,g_hcl);
  cudaGetSymbolAddress((void**)&phh, g_hh);  cudaGetSymbolAddress((void**)&phl, g_hl);
  cudaGetSymbolAddress((void**)&pWeh,g_Weh); cudaGetSymbolAddress((void**)&pWel,g_Wel);
  cudaGetSymbolAddress((void**)&pW1h,g_W1h); cudaGetSymbolAddress((void**)&pW1l,g_W1l);
  cudaGetSymbolAddress((void**)&pW2h,g_W2h); cudaGetSymbolAddress((void**)&pW2l,g_W2l);

  cudaFuncSetAttribute(gemm_k<0>, cudaFuncAttributeMaxDynamicSharedMemorySize, SMEM_BYTES);
  cudaFuncSetAttribute(gemm_k<1>, cudaFuncAttributeMaxDynamicSharedMemorySize, SMEM_BYTES);
  cudaFuncSetAttribute(gemm_k<2>, cudaFuncAttributeMaxDynamicSharedMemorySize, SMEM_BYTES);

  // launch order arranged so gemm_k<0> is launch index 3 (the profiled slot)
  aconv<<<((M1*64)+255)/256, 256>>>(vec, pvh, pvl, M1*64);            // 0
  wconv<<<(256*512+255)/256, 256>>>(We, pWeh, pWel, 256, 512);        // 1
  wconv<<<(512*256+255)/256, 256>>>(W1, pW1h, pW1l, 512, 256);        // 2
  gemm_k<0><<<dim3(4,(M1+127)/128), 256, SMEM_BYTES>>>(               // 3 <- profiled
      pvh, pvl, pWeh, pWel, (const float*)0, pv, (void*)0, M1, 256, 512);
  glue1<<<n, 256>>>(x, n);                                            // 4
  wconv<<<(256*768+255)/256, 256>>>(W2, pW2h, pW2l, 256, 768);        // 5
  gemm_k<1><<<dim3(2,(n+127)/128), 256, SMEM_BYTES>>>(                // 6
      phch, phcl, pW1h, pW1l, b1, phh, phl, n, 512, 256);
  gemm_k<2><<<dim3(6,(n+127)/128), 256, SMEM_BYTES>>>(                // 7
      phh, phl, pW2h, pW2l, b2, pxv, (void*)0, n, 256, 768);
  glue2<<<n, 256>>>(out, n);                                          // 8
}

// round 12
// speedup vs baseline: 1.4905x; 1.3200x over previous
#include <cuda_runtime.h>
#include <cuda_fp16.h>
#include <math.h>

typedef unsigned int u32; typedef unsigned long long u64;

#define MAXN 100096
#define MAXM (3*MAXN)
__device__ float g_v  [(size_t)MAXN*1536];
__device__ float g_xv [(size_t)MAXN*768];
__device__ float g_dot[(size_t)MAXN*256];
__device__ __half g_vf [(size_t)MAXM*256];   // vec as fp16
__device__ __half g_hc [(size_t)MAXN*512];   // hcat fp16
__device__ __half g_hf [(size_t)MAXN*256];   // h fp16
__device__ __half g_Weh[512*256], g_Wel[512*256];  // [n][k] hi/lo
__device__ __half g_W1h[256*512], g_W1l[256*512];
__device__ __half g_W2h[768*256], g_W2l[768*256];

#define RS 20
#define ASTRIDE 2560
#define SMEM_BYTES (9*ASTRIDE*4)    // 3 stages x 3 arrays x 10KB = 90KB

__device__ __forceinline__ void mma16816(float* d, const u32* a, u32 b0, u32 b1){
  asm volatile("mma.sync.aligned.m16n8k16.row.col.f32.f16.f16.f32 "
    "{%0,%1,%2,%3},{%4,%5,%6,%7},{%8,%9},{%0,%1,%2,%3};"
    : "+f"(d[0]),"+f"(d[1]),"+f"(d[2]),"+f"(d[3])
    : "r"(a[0]),"r"(a[1]),"r"(a[2]),"r"(a[3]),"r"(b0),"r"(b1));
}
__device__ __forceinline__ void ldm4(u32* r, u32 addr){
  asm volatile("ldmatrix.sync.aligned.m8n8.x4.shared.b16 {%0,%1,%2,%3},[%4];"
    : "=r"(r[0]),"=r"(r[1]),"=r"(r[2]),"=r"(r[3]) : "r"(addr));
}
__device__ __forceinline__ void ldm2(u32 &r0, u32 &r1, u32 addr){
  asm volatile("ldmatrix.sync.aligned.m8n8.x2.shared.b16 {%0,%1},[%2];"
    : "=r"(r0),"=r"(r1) : "r"(addr));
}
__device__ __forceinline__ u32 s2u(const void* p){ u32 a;
  asm("{.reg .u64 t; cvta.to.shared.u64 t,%1; cvt.u32.u64 %0,t;}":"=r"(a):"l"(p)); return a; }
__device__ __forceinline__ void cpa16(u32 dst, const void* src){
  asm volatile("cp.async.cg.shared.global [%0], [%1], 16;" :: "r"(dst), "l"(src));
}
__device__ __forceinline__ u32 h2pack(float a, float b){
  __half2 h = __halves2half2(__float2half_rn(a), __float2half_rn(b));
  return *(u32*)&h;
}

// MODE 0: fp32 out. MODE 1: +bias, silu -> fp16 out. MODE 2: +bias fp32 out.
template<int MODE>
__global__ void __launch_bounds__(256, 2)
gemm_k(const __half* __restrict__ Af,
       const __half* __restrict__ Bh, const __half* __restrict__ Bl,
       const float* __restrict__ bias,
       void* o0, int M, int K, int N)
{
  extern __shared__ u32 sm[];
  const u32 sbase = s2u(sm);
  const int tid = threadIdx.x, lane = tid & 31, wid = tid >> 5;
  const int wm = (wid & 1) * 64, wn = (wid >> 1) * 32;
  const int m0 = blockIdx.y * 128, n0 = blockIdx.x * 128;
  const int g = lane >> 2, qq = lane & 3;
  const int NK = K >> 5;

  float acc[4][4][4];
  #pragma unroll
  for (int a=0;a<4;a++) for (int b=0;b<4;b++) for (int c=0;c<4;c++) acc[a][b][c]=0.f;

  auto stage = [&](int s, int kc){
    #pragma unroll
    for (int a = 0; a < 3; a++){
      #pragma unroll
      for (int q = 0; q < 2; q++){
        const int idx = q*256 + tid;         // 512 16B-chunks per array
        const int row = idx >> 2, ch = idx & 3;
        const u32 dst = sbase + ((s*3 + a)*ASTRIDE + row*RS + ch*4) * 4;
        const __half* src;
        if (a == 0){
          int gr = m0 + row; if (gr >= M) gr = M - 1;
          src = Af + (size_t)gr * K + kc + ch*8;
        } else {
          src = (a == 1 ? Bh : Bl) + (size_t)(n0 + row) * K + kc + ch*8;
        }
        cpa16(dst, src);
      }
    }
    asm volatile("cp.async.commit_group;" ::: "memory");
  };

  const int aoff = (wm + (lane & 7) + ((lane >> 3) & 1) * 8) * RS + ((lane >> 4) & 1) * 4;
  const int boff = (wn + (lane & 7)) * RS + ((lane >> 3) & 1) * 4;

  stage(0, 0);
  if (NK > 1) stage(1, 32);
  for (int it = 0; it < NK; it++){
    if (it + 1 < NK) { asm volatile("cp.async.wait_group 1;" ::: "memory"); }
    else             { asm volatile("cp.async.wait_group 0;" ::: "memory"); }
    __syncthreads();
    if (it + 2 < NK) stage((it + 2) % 3, (it + 2) << 5);

    const u32 base = sbase + ((it % 3) * 3) * ASTRIDE * 4;
    const u32 bA = base, bBh = base + ASTRIDE*4, bBl = base + 2*ASTRIDE*4;
    #pragma unroll
    for (int k16 = 0; k16 < 2; k16++){
      const int kof  = (aoff + k16*8) * 4;
      const int kofb = (boff + k16*8) * 4;
      u32 a[4][4];
      #pragma unroll
      for (int fm = 0; fm < 4; fm++)
        ldm4(a[fm], bA + kof + fm*16*RS*4);
      #pragma unroll
      for (int fn = 0; fn < 4; fn++){
        u32 bh0, bh1, bl0, bl1;
        ldm2(bh0, bh1, bBh + kofb + fn*8*RS*4);
        ldm2(bl0, bl1, bBl + kofb + fn*8*RS*4);
        #pragma unroll
        for (int fm = 0; fm < 4; fm++){
          mma16816(acc[fm][fn], a[fm], bh0, bh1);
          mma16816(acc[fm][fn], a[fm], bl0, bl1);
        }
      }
    }
  }

  #pragma unroll
  for (int fm = 0; fm < 4; fm++)
    #pragma unroll
    for (int half = 0; half < 2; half++){
      const int row = m0 + wm + fm*16 + g + half*8;
      if (row >= M) continue;
      #pragma unroll
      for (int fn = 0; fn < 4; fn++){
        const int col = n0 + wn + fn*8 + 2*qq;
        float v0 = acc[fm][fn][half*2], v1 = acc[fm][fn][half*2+1];
        if (MODE == 0){
          *(float2*)&((float*)o0)[(size_t)row*N + col] = make_float2(v0, v1);
        } else if (MODE == 1){
          float2 bb = *(const float2*)(bias + col);
          v0 += bb.x; v1 += bb.y;
          v0 = v0 / (1.f + __expf(-v0));
          v1 = v1 / (1.f + __expf(-v1));
          ((u32*)o0)[((size_t)row*N + col) >> 1] = h2pack(v0, v1);
        } else {
          float2 bb = *(const float2*)(bias + col);
          *(float2*)&((float*)o0)[(size_t)row*N + col] =
              make_float2(v0 + bb.x, v1 + bb.y);
        }
      }
    }
}

__global__ void wconv(const float* __restrict__ W, __half* Wh, __half* Wl, int K, int N){
  int idx = blockIdx.x*256 + threadIdx.x;
  if (idx >= K*N) return;
  int k = idx / N, nn = idx - k*N;
  float f = W[idx];
  __half h = __float2half_rn(f);
  Wh[(size_t)nn*K + k] = h;
  Wl[(size_t)nn*K + k] = __float2half_rn(f - __half2float(h));
}
__global__ void aconv(const float* __restrict__ A, __half* Af, int n4){
  int i = blockIdx.x*256 + threadIdx.x;
  if (i >= n4) return;
  float4 v = ((const float4*)A)[i];
  ((uint2*)Af)[i] = make_uint2(h2pack(v.x, v.y), h2pack(v.z, v.w));
}
__global__ void glue1(const float* __restrict__ x, int n){
  int nd = blockIdx.x, j = threadIdx.x;
  const float* vr = g_v + (size_t)nd*1536;
  float a0=vr[j], a1=vr[512+j], a2=vr[1024+j];
  float b0=vr[256+j], b1=vr[768+j], b2=vr[1280+j];
  float xx = x[(size_t)nd*256 + j];
  float sc = sqrtf(a0*a0 + a1*a1 + a2*a2);
  g_dot[(size_t)nd*256 + j] = (a0*b0 + a1*b1 + a2*b2) * 0.0625f;
  g_hc[(size_t)nd*512 + j]       = __float2half_rn(xx);
  g_hc[(size_t)nd*512 + 256 + j] = __float2half_rn(sc);
}
__global__ void glue2(float* __restrict__ out, int n){
  int nd = blockIdx.x, j = threadIdx.x;
  const float* xv = g_xv + (size_t)nd*768;
  float x1 = xv[j], x2 = xv[256+j], x3 = xv[512+j];
  out[(size_t)nd*256 + j] = (x1 + x2 + g_dot[(size_t)nd*256+j]) * 0.70710678118654752f;
  const float* vr = g_v + (size_t)nd*1536 + 256;
  float* dv = out + (size_t)n*256 + (size_t)nd*768;
  dv[j]     = x3 * vr[j];
  dv[256+j] = x3 * vr[512+j];
  dv[512+j] = x3 * vr[1024+j];
}

extern "C" void kernel_launch(void* const* d_in, const int* in_sizes, int n_in,
                              void* d_out, int out_size)
{
  const float* x   = (const float*)d_in[0];
  const float* vec = (const float*)d_in[1];
  const float* We  = (const float*)d_in[3];
  const float* W1  = (const float*)d_in[4];
  const float* b1  = (const float*)d_in[5];
  const float* W2  = (const float*)d_in[6];
  const float* b2  = (const float*)d_in[7];
  float* out = (float*)d_out;
  const int n = in_sizes[0] / 256;
  const int M1 = 3*n;

  float *pv, *pxv;
  __half *pvf,*phc,*phf,*pWeh,*pWel,*pW1h,*pW1l,*pW2h,*pW2l;
  cudaGetSymbolAddress((void**)&pv,  g_v);   cudaGetSymbolAddress((void**)&pxv, g_xv);
  cudaGetSymbolAddress((void**)&pvf, g_vf);
  cudaGetSymbolAddress((void**)&phc, g_hc);  cudaGetSymbolAddress((void**)&phf, g_hf);
  cudaGetSymbolAddress((void**)&pWeh,g_Weh); cudaGetSymbolAddress((void**)&pWel,g_Wel);
  cudaGetSymbolAddress((void**)&pW1h,g_W1h); cudaGetSymbolAddress((void**)&pW1l,g_W1l);
  cudaGetSymbolAddress((void**)&pW2h,g_W2h); cudaGetSymbolAddress((void**)&pW2l,g_W2l);

  cudaFuncSetAttribute(gemm_k<0>, cudaFuncAttributeMaxDynamicSharedMemorySize, SMEM_BYTES);
  cudaFuncSetAttribute(gemm_k<1>, cudaFuncAttributeMaxDynamicSharedMemorySize, SMEM_BYTES);
  cudaFuncSetAttribute(gemm_k<2>, cudaFuncAttributeMaxDynamicSharedMemorySize, SMEM_BYTES);

  // launch order keeps gemm_k<0> at index 3 (profiled slot)
  aconv<<<((M1*64)+255)/256, 256>>>(vec, pvf, M1*64);                 // 0
  wconv<<<(256*512+255)/256, 256>>>(We, pWeh, pWel, 256, 512);        // 1
  wconv<<<(512*256+255)/256, 256>>>(W1, pW1h, pW1l, 512, 256);        // 2
  gemm_k<0><<<dim3(4,(M1+127)/128), 256, SMEM_BYTES>>>(               // 3 <- profiled
      pvf, pWeh, pWel, (const float*)0, pv, M1, 256, 512);
  glue1<<<n, 256>>>(x, n);                                            // 4
  wconv<<<(256*768+255)/256, 256>>>(W2, pW2h, pW2l, 256, 768);        // 5
  gemm_k<1><<<dim3(2,(n+127)/128), 256, SMEM_BYTES>>>(                // 6
      phc, pW1h, pW1l, b1, phf, n, 512, 256);
  gemm_k<2><<<dim3(6,(n+127)/128), 256, SMEM_BYTES>>>(                // 7
      phf, pW2h, pW2l, b2, pxv, n, 256, 768);
  glue2<<<n, 256>>>(out, n);                                          // 8
}